// round 12
// baseline (speedup 1.0000x reference)
#include <cuda_runtime.h>
#include <cuda_fp16.h>
#include <math.h>
#include <stdint.h>

#define S_LEN  4096
#define DM     2048
#define NH     16
#define NKV    4
#define HD     128
#define QKVW   3072          // fused qkv width

// ---------------- scratch (device globals; no runtime alloc allowed) --------
__device__ float g_qkv[(size_t)S_LEN * QKVW];          // 48 MB  q|k|v fused
__device__ uint4 g_pa[(size_t)S_LEN * DM / 8];         // packed x (fp16 A blobs)
__device__ uint4 g_pattn[(size_t)S_LEN * DM / 8];      // packed attn (A blobs)
__device__ uint4 g_pbqkv[(size_t)QKVW * DM / 8];       // packed wq|wk|wv (B4 blobs)
__device__ uint4 g_pbwo[(size_t)DM * DM / 8];          // packed wo (B4 blobs)
__device__ float2 g_rope[(size_t)S_LEN * 64];          // cos/sin table
__device__ uint2 g_kf[(size_t)NKV * 64 * 2048];        // packed K frag blobs (4MB)
__device__ uint2 g_vf[(size_t)NKV * 64 * 2048];        // packed V frag blobs (4MB)

// ---------------- helpers ----------------------------------------------------
__device__ __forceinline__ uint32_t f2h2(float a, float b) {
  __half2 h = __floats2half2_rn(a, b);   // x=a (low), y=b (high)
  return *(uint32_t*)&h;
}

__device__ __forceinline__ void mma_f16(float* c, const uint32_t* a,
                                        const uint32_t* b) {
  asm volatile(
      "mma.sync.aligned.m16n8k16.row.col.f32.f16.f16.f32 "
      "{%0,%1,%2,%3}, {%4,%5,%6,%7}, {%8,%9}, {%0,%1,%2,%3};"
      : "+f"(c[0]), "+f"(c[1]), "+f"(c[2]), "+f"(c[3])
      : "r"(a[0]), "r"(a[1]), "r"(a[2]), "r"(a[3]), "r"(b[0]), "r"(b[1]));
}

__device__ __forceinline__ void cp16(uint32_t s, const void* g) {
  asm volatile("cp.async.cg.shared.global [%0], [%1], 16;" ::"r"(s), "l"(g));
}

__device__ __forceinline__ uint32_t smem_u32(const void* p) {
  uint32_t a;
  asm("{ .reg .u64 t; cvta.to.shared.u64 t, %1; cvt.u32.u64 %0, t; }"
      : "=r"(a) : "l"(p));
  return a;
}

// ---------------- fp16 pack kernels -----------------------------------------
__global__ __launch_bounds__(256) void pack_a_f16(const float* __restrict__ A,
                                                  uint4* __restrict__ P, int K) {
  const int kt = blockIdx.x, mb = blockIdx.y, tid = threadIdx.x;
  const int T = gridDim.x;
  uint4* out = P + ((size_t)mb * T + kt) * 1024;
#pragma unroll
  for (int idx = tid; idx < 1024; idx += 256) {
    const int s = idx >> 8, m = (idx >> 5) & 7, l = idx & 31;
    const int g = l >> 2, t = l & 3;
    const int row0 = mb * 128 + m * 16 + g;
    const int kb = kt * 64 + s * 16 + 2 * t;
    const float* r0 = A + (size_t)row0 * K + kb;
    const float* r1 = r0 + (size_t)8 * K;
    uint4 u;
    u.x = f2h2(r0[0], r0[1]);
    u.y = f2h2(r1[0], r1[1]);
    u.z = f2h2(r0[8], r0[9]);
    u.w = f2h2(r1[8], r1[9]);
    out[idx] = u;
  }
}

// B blob per (nband, kt64): [s4][npair8][lane32] x uint4 = 16 KB
__global__ __launch_bounds__(256) void pack_b_f16(const float* __restrict__ W,
                                                  uint4* __restrict__ P, int Nin,
                                                  int noff) {
  const int kt = blockIdx.x, nb = blockIdx.y, tid = threadIdx.x;
  const int T = gridDim.x;
  uint4* out = P + ((size_t)(nb + noff) * T + kt) * 1024;
#pragma unroll
  for (int idx = tid; idx < 1024; idx += 256) {
    const int s = idx >> 8, np = (idx >> 5) & 7, l = idx & 31;
    const int t = l & 3;
    const int c0 = nb * 128 + np * 16 + (l >> 2);
    const int kb = kt * 64 + s * 16 + 2 * t;
    const float* w0 = W + (size_t)kb * Nin + c0;
    uint4 u;
    u.x = f2h2(w0[0], w0[Nin]);
    u.y = f2h2(w0[(size_t)8 * Nin], w0[(size_t)9 * Nin]);
    u.z = f2h2(w0[8], w0[Nin + 8]);
    u.w = f2h2(w0[(size_t)8 * Nin + 8], w0[(size_t)9 * Nin + 8]);
    out[idx] = u;
  }
}

// pack roped K and V into flash fragment blobs, once per (kvh, kv-tile)
__global__ __launch_bounds__(256) void pack_kv(const float* __restrict__ qkv) {
  const int t = blockIdx.x;    // kv tile 0..63
  const int kvh = blockIdx.y;  // 0..3
  const int tid = threadIdx.x;
  const float* Kp = qkv + DM + kvh * HD;
  const float* Vp = qkv + DM + NKV * HD + kvh * HD;
  uint2* ko = g_kf + ((size_t)kvh * 64 + t) * 2048;
  uint2* vo = g_vf + ((size_t)kvh * 64 + t) * 2048;
#pragma unroll
  for (int e = tid; e < 2048; e += 256) {
    const int l = e & 31, g = l >> 2, tt = l & 3;
    {
      const int nt = (e >> 5) & 7, ks = e >> 8;
      const float* kr = Kp + (size_t)(t * 64 + 8 * nt + g) * QKVW + 16 * ks + 2 * tt;
      uint2 u;
      u.x = f2h2(kr[0], kr[1]);
      u.y = f2h2(kr[8], kr[9]);
      ko[e] = u;
    }
    {
      const int nt = (e >> 5) & 15, ks = e >> 9;
      const int d = nt * 8 + g;
      const float* vr = Vp + (size_t)(t * 64 + ks * 16 + 2 * tt) * QKVW + d;
      uint2 u;
      u.x = f2h2(vr[0], vr[QKVW]);
      u.y = f2h2(vr[(size_t)8 * QKVW], vr[(size_t)9 * QKVW]);
      vo[e] = u;
    }
  }
}

// ---------------- packed fp16 GEMM: 128x256 tile, BK=128, 512 thr -----------
// Warp grid 4x4, warp tile 32x64, 8 k-steps/phase -> 128 mma/warp/phase.
// Stage = A 32KB + B 64KB = 96KB; 2 stages = 192KB; 1 CTA/SM.
#define GEMM_SMEM (2 * 98304)
__global__ __launch_bounds__(512, 1) void gemm_f16(
    const uint4* __restrict__ Ap, const uint4* __restrict__ Bp,
    float* __restrict__ C, int N, int K) {
  extern __shared__ uint32_t sm[];
  const int tid = threadIdx.x;
  const int l = tid & 31;
  const int w = tid >> 5;          // 0..15
  const int warp_m = w >> 2;       // 0..3
  const int warp_n = w & 3;        // 0..3
  const int T = K >> 7;            // 128-k phases
  const int Tk = K >> 6;           // 64-k blobs

  const uint4* Ag = Ap + (size_t)blockIdx.y * Tk * 1024;
  const uint4* Bg0 = Bp + (size_t)(blockIdx.x * 2) * Tk * 1024;
  const uint4* Bg1 = Bg0 + (size_t)Tk * 1024;
  const uint32_t smu = smem_u32(sm);

  float acc[2][8][4];
#pragma unroll
  for (int mt = 0; mt < 2; mt++)
#pragma unroll
    for (int nt = 0; nt < 8; nt++)
#pragma unroll
      for (int c = 0; c < 4; c++) acc[mt][nt][c] = 0.0f;

  // stage layout (uint4 idx): A[0..2047] = 2 blobs; B[2048+nb*2048+..] = 4 blobs
#define CPT(p)                                                                 \
  do {                                                                         \
    const uint32_t ba = smu + ((p) & 1) * 98304;                               \
    const uint4* ga = Ag + (size_t)(p) * 2048;                                 \
    const uint4* gb0 = Bg0 + (size_t)(p) * 2048;                               \
    const uint4* gb1 = Bg1 + (size_t)(p) * 2048;                               \
    _Pragma("unroll") for (int j = 0; j < 4; j++) {                            \
      cp16(ba + (tid + 512 * j) * 16, ga + tid + 512 * j);                     \
      cp16(ba + 32768 + (tid + 512 * j) * 16, gb0 + tid + 512 * j);            \
      cp16(ba + 65536 + (tid + 512 * j) * 16, gb1 + tid + 512 * j);            \
    }                                                                          \
    asm volatile("cp.async.commit_group;");                                    \
  } while (0)

  CPT(0);

  const int nbo = warp_n >> 1;         // which B blob pair (0/1)
  const int npb = (warp_n & 1) * 4;    // np base within blob

  for (int p = 0; p < T; p++) {
    asm volatile("cp.async.wait_group 0;");
    __syncthreads();
    if (p + 1 < T) CPT(p + 1);

    const uint4* smA = (const uint4*)(sm + (p & 1) * 24576);
    const uint4* smB = smA + 2048 + nbo * 2048;
#pragma unroll
    for (int ks = 0; ks < 8; ks++) {
      const int half = ks >> 2, s = ks & 3;
      uint4 af[2];
#pragma unroll
      for (int mt = 0; mt < 2; mt++)
        af[mt] = smA[half * 1024 + (s * 8 + warp_m * 2 + mt) * 32 + l];
      uint4 bq[4];
#pragma unroll
      for (int j = 0; j < 4; j++)
        bq[j] = smB[half * 1024 + (s * 8 + npb + j) * 32 + l];
      const uint32_t bfr[8][2] = {{bq[0].x, bq[0].y}, {bq[0].z, bq[0].w},
                                  {bq[1].x, bq[1].y}, {bq[1].z, bq[1].w},
                                  {bq[2].x, bq[2].y}, {bq[2].z, bq[2].w},
                                  {bq[3].x, bq[3].y}, {bq[3].z, bq[3].w}};
#pragma unroll
      for (int mt = 0; mt < 2; mt++) {
        const uint32_t a[4] = {af[mt].x, af[mt].y, af[mt].z, af[mt].w};
#pragma unroll
        for (int nt = 0; nt < 8; nt++) mma_f16(acc[mt][nt], a, bfr[nt]);
      }
    }
  }

  const int bm = blockIdx.y * 128;
  const int bn = blockIdx.x * 256;
#pragma unroll
  for (int mt = 0; mt < 2; mt++) {
    const int row = bm + warp_m * 32 + mt * 16 + (l >> 2);
#pragma unroll
    for (int nt = 0; nt < 8; nt++) {
      const int col = bn + warp_n * 64 + nt * 8 + 2 * (l & 3);
      float2 lo = {acc[mt][nt][0], acc[mt][nt][1]};
      float2 hi = {acc[mt][nt][2], acc[mt][nt][3]};
      *(float2*)(C + (size_t)row * N + col) = lo;
      *(float2*)(C + (size_t)(row + 8) * N + col) = hi;
    }
  }
}

// ---------------- RoPE: table + apply ----------------------------------------
__global__ __launch_bounds__(256) void rope_table_kernel() {
  const int idx = blockIdx.x * 256 + threadIdx.x;
  const int s = idx >> 6, d = idx & 63;
  float inv = powf(10000.0f, -((float)(2 * d) / 128.0f));
  float sn, cs;
  sincosf((float)s * inv, &sn, &cs);
  g_rope[idx] = make_float2(cs, sn);
}

__global__ __launch_bounds__(256) void rope_apply_kernel(float* __restrict__ qkv) {
  const int tid = threadIdx.x;
  const int d = tid & 63, si = tid >> 6;
  const int s = blockIdx.x * 4 + si;
  const int hh = blockIdx.y;
  float* ptr = qkv + (size_t)s * QKVW +
               (hh < NH ? hh * HD : DM + (hh - NH) * HD);
  const float2 cs = g_rope[s * 64 + d];
  const float x0 = ptr[d];
  const float x1 = ptr[d + 64];
  ptr[d] = x0 * cs.x - x1 * cs.y;
  ptr[d + 64] = x1 * cs.x + x0 * cs.y;
}

// ---------------- Flash attention, fp16 m16n8k16, cp.async KV pipeline ------
#define BQ 128
#define BKV 64
#define F_SMEM_BYTES (32768 + 2 * 32768)

__global__ __launch_bounds__(256) void flash_f16_kernel(
    const float* __restrict__ QKV, uint4* __restrict__ Pout) {
  extern __shared__ uint32_t fsm[];
  uint4* Qf = (uint4*)fsm;                 // 8192 words

  const int h = blockIdx.y;
  const int qb = gridDim.x - 1 - blockIdx.x;  // long blocks first
  const int q0 = qb * BQ;
  const int kvh = h >> 2;
  const int tid = threadIdx.x;
  const int l = tid & 31;
  const int w = tid >> 5;
  const int g = l >> 2;
  const int tt = l & 3;

  const float* Qp = QKV + h * HD;
  const float scale = 0.08838834764831845f;
  const uint32_t smu = smem_u32(fsm);
  const uint4* kvbase_k = (const uint4*)(g_kf + (size_t)kvh * 64 * 2048);
  const uint4* kvbase_v = (const uint4*)(g_vf + (size_t)kvh * 64 * 2048);

#define CPKV(t)                                                                \
  do {                                                                         \
    const uint32_t ba = smu + 32768 + ((t) & 1) * 32768;                       \
    const uint4* kg = kvbase_k + (size_t)(t) * 1024;                           \
    const uint4* vg = kvbase_v + (size_t)(t) * 1024;                           \
    _Pragma("unroll") for (int j = 0; j < 4; j++) {                            \
      cp16(ba + (tid + 256 * j) * 16, kg + tid + 256 * j);                     \
      cp16(ba + 16384 + (tid + 256 * j) * 16, vg + tid + 256 * j);             \
    }                                                                          \
    asm volatile("cp.async.commit_group;");                                    \
  } while (0)

  CPKV(0);

#pragma unroll
  for (int i = 0; i < 8; i++) {
    const float* r0 = Qp + (size_t)(q0 + 16 * w + g) * QKVW + 16 * i + 2 * tt;
    const float* r1 = r0 + (size_t)8 * QKVW;
    float2 x0 = *(const float2*)r0;
    float2 x1 = *(const float2*)(r0 + 8);
    float2 y0 = *(const float2*)r1;
    float2 y1 = *(const float2*)(r1 + 8);
    uint4 u;
    u.x = f2h2(x0.x * scale, x0.y * scale);
    u.y = f2h2(y0.x * scale, y0.y * scale);
    u.z = f2h2(x1.x * scale, x1.y * scale);
    u.w = f2h2(y1.x * scale, y1.y * scale);
    Qf[tid + 256 * i] = u;
  }

  float m_i0 = -3.0e38f, m_i1 = -3.0e38f;
  float l_i0 = 0.0f, l_i1 = 0.0f;
  float O[16][4];
#pragma unroll
  for (int nt = 0; nt < 16; nt++)
#pragma unroll
    for (int c = 0; c < 4; c++) O[nt][c] = 0.0f;

  const int ntiles = (q0 + BQ) / BKV;

  for (int t = 0; t < ntiles; t++) {
    asm volatile("cp.async.wait_group 0;");
    __syncthreads();
    if (t + 1 < ntiles) CPKV(t + 1);

    const uint2* Kf = (const uint2*)(fsm + 8192 + (t & 1) * 8192);
    const uint2* Vf = (const uint2*)(fsm + 8192 + (t & 1) * 8192 + 4096);

    const bool active = (t * BKV <= q0 + 16 * w + 15);
    if (active) {
      float S[8][4];
#pragma unroll
      for (int nt = 0; nt < 8; nt++)
#pragma unroll
        for (int c = 0; c < 4; c++) S[nt][c] = 0.0f;
#pragma unroll
      for (int ks = 0; ks < 8; ks++) {
        uint4 af = Qf[(ks * 8 + w) * 32 + l];
        const uint32_t a[4] = {af.x, af.y, af.z, af.w};
#pragma unroll
        for (int nt = 0; nt < 8; nt++) {
          uint2 bf = Kf[(ks * 8 + nt) * 32 + l];
          const uint32_t b[2] = {bf.x, bf.y};
          mma_f16(S[nt], a, b);
        }
      }

      const int rowg0 = q0 + 16 * w + g;
      const int rowg1 = rowg0 + 8;
      if (t * BKV + BKV - 1 > q0 + 16 * w) {
#pragma unroll
        for (int nt = 0; nt < 8; nt++) {
          const int c0 = t * BKV + nt * 8 + 2 * tt;
          if (c0 > rowg0) S[nt][0] = -3.0e38f;
          if (c0 + 1 > rowg0) S[nt][1] = -3.0e38f;
          if (c0 > rowg1) S[nt][2] = -3.0e38f;
          if (c0 + 1 > rowg1) S[nt][3] = -3.0e38f;
        }
      }

      float mx0 = -3.0e38f, mx1 = -3.0e38f;
#pragma unroll
      for (int nt = 0; nt < 8; nt++) {
        mx0 = fmaxf(mx0, fmaxf(S[nt][0], S[nt][1]));
        mx1 = fmaxf(mx1, fmaxf(S[nt][2], S[nt][3]));
      }
      mx0 = fmaxf(mx0, __shfl_xor_sync(0xffffffffu, mx0, 1));
      mx0 = fmaxf(mx0, __shfl_xor_sync(0xffffffffu, mx0, 2));
      mx1 = fmaxf(mx1, __shfl_xor_sync(0xffffffffu, mx1, 1));
      mx1 = fmaxf(mx1, __shfl_xor_sync(0xffffffffu, mx1, 2));
      const float mn0 = fmaxf(m_i0, mx0);
      const float mn1 = fmaxf(m_i1, mx1);

      float rs0 = 0.0f, rs1 = 0.0f;
#pragma unroll
      for (int nt = 0; nt < 8; nt++) {
        S[nt][0] = __expf(S[nt][0] - mn0);
        S[nt][1] = __expf(S[nt][1] - mn0);
        S[nt][2] = __expf(S[nt][2] - mn1);
        S[nt][3] = __expf(S[nt][3] - mn1);
        rs0 += S[nt][0] + S[nt][1];
        rs1 += S[nt][2] + S[nt][3];
      }
      rs0 += __shfl_xor_sync(0xffffffffu, rs0, 1);
      rs0 += __shfl_xor_sync(0xffffffffu, rs0, 2);
      rs1 += __shfl_xor_sync(0xffffffffu, rs1, 1);
      rs1 += __shfl_xor_sync(0xffffffffu, rs1, 2);
      const float alpha0 = __expf(m_i0 - mn0);
      const float alpha1 = __expf(m_i1 - mn1);
      l_i0 = l_i0 * alpha0 + rs0;
      l_i1 = l_i1 * alpha1 + rs1;
      m_i0 = mn0;
      m_i1 = mn1;
#pragma unroll
      for (int nt = 0; nt < 16; nt++) {
        O[nt][0] *= alpha0;
        O[nt][1] *= alpha0;
        O[nt][2] *= alpha1;
        O[nt][3] *= alpha1;
      }

#pragma unroll
      for (int ks = 0; ks < 4; ks++) {
        const uint32_t a[4] = {f2h2(S[2 * ks][0], S[2 * ks][1]),
                               f2h2(S[2 * ks][2], S[2 * ks][3]),
                               f2h2(S[2 * ks + 1][0], S[2 * ks + 1][1]),
                               f2h2(S[2 * ks + 1][2], S[2 * ks + 1][3])};
#pragma unroll
        for (int nt = 0; nt < 16; nt++) {
          uint2 bf = Vf[(ks * 16 + nt) * 32 + l];
          const uint32_t b[2] = {bf.x, bf.y};
          mma_f16(O[nt], a, b);
        }
      }
    }
    __syncthreads();
  }

  const float inv0 = 1.0f / l_i0;
  const float inv1 = 1.0f / l_i1;
  uint4* outp = Pout + (size_t)qb * 32 * 1024;
#pragma unroll
  for (int p = 0; p < 8; p++) {
    const int nt = 2 * p;
    const int kt = 2 * h + (nt >> 3);
    const int s = (nt & 7) >> 1;
    uint4 u;
    u.x = f2h2(O[nt][0] * inv0, O[nt][1] * inv0);
    u.y = f2h2(O[nt][2] * inv1, O[nt][3] * inv1);
    u.z = f2h2(O[nt + 1][0] * inv0, O[nt + 1][1] * inv0);
    u.w = f2h2(O[nt + 1][2] * inv1, O[nt + 1][3] * inv1);
    outp[(size_t)kt * 1024 + s * 256 + w * 32 + l] = u;
  }
}

// ---------------- launch ----------------------------------------------------
extern "C" void kernel_launch(void* const* d_in, const int* in_sizes, int n_in,
                              void* d_out, int out_size) {
  const float* x = (const float*)d_in[0];
  const float* wq = (const float*)d_in[1];
  const float* wk = (const float*)d_in[2];
  const float* wv = (const float*)d_in[3];
  const float* wo = (const float*)d_in[4];
  float* out = (float*)d_out;

  float* qkv_p;
  uint4 *pa, *pattn, *pbqkv, *pbwo;
  cudaGetSymbolAddress((void**)&qkv_p, g_qkv);
  cudaGetSymbolAddress((void**)&pa, g_pa);
  cudaGetSymbolAddress((void**)&pattn, g_pattn);
  cudaGetSymbolAddress((void**)&pbqkv, g_pbqkv);
  cudaGetSymbolAddress((void**)&pbwo, g_pbwo);

  cudaFuncSetAttribute(gemm_f16, cudaFuncAttributeMaxDynamicSharedMemorySize,
                       GEMM_SMEM);
  cudaFuncSetAttribute(flash_f16_kernel,
                       cudaFuncAttributeMaxDynamicSharedMemorySize,
                       F_SMEM_BYTES);

  // packs
  pack_a_f16<<<dim3(DM / 64, S_LEN / 128), 256>>>(x, pa, DM);
  pack_b_f16<<<dim3(DM / 64, 16), 256>>>(wq, pbqkv, DM, 0);
  pack_b_f16<<<dim3(DM / 64, 4), 256>>>(wk, pbqkv, NKV * HD, 16);
  pack_b_f16<<<dim3(DM / 64, 4), 256>>>(wv, pbqkv, NKV * HD, 20);
  pack_b_f16<<<dim3(DM / 64, 16), 256>>>(wo, pbwo, DM, 0);

  // fused QKV projection: [4096,2048] x [2048,3072], 128x256 tiles
  gemm_f16<<<dim3(QKVW / 256, S_LEN / 128), 512, GEMM_SMEM>>>(pa, pbqkv, qkv_p,
                                                              QKVW, DM);

  // RoPE table + apply
  rope_table_kernel<<<(S_LEN * 64) / 256, 256>>>();
  rope_apply_kernel<<<dim3(S_LEN / 4, NH + NKV), 256>>>(qkv_p);

  // pack roped K/V into fp16 fragment blobs (once)
  pack_kv<<<dim3(S_LEN / BKV, NKV), 256>>>(qkv_p);

  // causal flash attention (fp16 mma, cp.async KV pipeline, packed-out)
  flash_f16_kernel<<<dim3(S_LEN / BQ, NH), 256, F_SMEM_BYTES>>>(qkv_p, pattn);

  // output projection (reads flash's packed output directly)
  gemm_f16<<<dim3(DM / 256, S_LEN / 128), 512, GEMM_SMEM>>>(pattn, pbwo, out,
                                                            DM, DM);
}

// round 13
// speedup vs baseline: 1.0267x; 1.0267x over previous
#include <cuda_runtime.h>
#include <cuda_fp16.h>
#include <math.h>
#include <stdint.h>

#define S_LEN  4096
#define DM     2048
#define NH     16
#define NKV    4
#define HD     128
#define QKVW   3072          // fused qkv width

// ---------------- scratch (device globals; no runtime alloc allowed) --------
__device__ float g_qkv[(size_t)S_LEN * QKVW];          // 48 MB  q|k|v fused
__device__ uint4 g_pa[(size_t)S_LEN * DM / 8];         // packed x (fp16 A blobs)
__device__ uint4 g_pattn[(size_t)S_LEN * DM / 8];      // packed attn (A blobs)
__device__ uint4 g_pbqkv[(size_t)QKVW * DM / 8];       // packed wq|wk|wv (B4 blobs)
__device__ uint4 g_pbwo[(size_t)DM * DM / 8];          // packed wo (B4 blobs)
__device__ float2 g_rope[(size_t)S_LEN * 64];          // cos/sin table
__device__ uint2 g_kf[(size_t)NKV * 64 * 2048];        // packed K frag blobs (4MB)
__device__ uint2 g_vf[(size_t)NKV * 64 * 2048];        // packed V frag blobs (4MB)

// ---------------- helpers ----------------------------------------------------
__device__ __forceinline__ uint32_t f2h2(float a, float b) {
  __half2 h = __floats2half2_rn(a, b);   // x=a (low), y=b (high)
  return *(uint32_t*)&h;
}

__device__ __forceinline__ void mma_f16(float* c, const uint32_t* a,
                                        const uint32_t* b) {
  asm volatile(
      "mma.sync.aligned.m16n8k16.row.col.f32.f16.f16.f32 "
      "{%0,%1,%2,%3}, {%4,%5,%6,%7}, {%8,%9}, {%0,%1,%2,%3};"
      : "+f"(c[0]), "+f"(c[1]), "+f"(c[2]), "+f"(c[3])
      : "r"(a[0]), "r"(a[1]), "r"(a[2]), "r"(a[3]), "r"(b[0]), "r"(b[1]));
}

__device__ __forceinline__ void cp16(uint32_t s, const void* g) {
  asm volatile("cp.async.cg.shared.global [%0], [%1], 16;" ::"r"(s), "l"(g));
}

__device__ __forceinline__ uint32_t smem_u32(const void* p) {
  uint32_t a;
  asm("{ .reg .u64 t; cvta.to.shared.u64 t, %1; cvt.u32.u64 %0, t; }"
      : "=r"(a) : "l"(p));
  return a;
}

// ---------------- fp16 pack kernels -----------------------------------------
__global__ __launch_bounds__(256) void pack_a_f16(const float* __restrict__ A,
                                                  uint4* __restrict__ P, int K) {
  const int kt = blockIdx.x, mb = blockIdx.y, tid = threadIdx.x;
  const int T = gridDim.x;
  uint4* out = P + ((size_t)mb * T + kt) * 1024;
#pragma unroll
  for (int idx = tid; idx < 1024; idx += 256) {
    const int s = idx >> 8, m = (idx >> 5) & 7, l = idx & 31;
    const int g = l >> 2, t = l & 3;
    const int row0 = mb * 128 + m * 16 + g;
    const int kb = kt * 64 + s * 16 + 2 * t;
    const float* r0 = A + (size_t)row0 * K + kb;
    const float* r1 = r0 + (size_t)8 * K;
    uint4 u;
    u.x = f2h2(r0[0], r0[1]);
    u.y = f2h2(r1[0], r1[1]);
    u.z = f2h2(r0[8], r0[9]);
    u.w = f2h2(r1[8], r1[9]);
    out[idx] = u;
  }
}

// B blob per (nband, kt64): [s4][npair8][lane32] x uint4 = 16 KB
__global__ __launch_bounds__(256) void pack_b_f16(const float* __restrict__ W,
                                                  uint4* __restrict__ P, int Nin,
                                                  int noff) {
  const int kt = blockIdx.x, nb = blockIdx.y, tid = threadIdx.x;
  const int T = gridDim.x;
  uint4* out = P + ((size_t)(nb + noff) * T + kt) * 1024;
#pragma unroll
  for (int idx = tid; idx < 1024; idx += 256) {
    const int s = idx >> 8, np = (idx >> 5) & 7, l = idx & 31;
    const int t = l & 3;
    const int c0 = nb * 128 + np * 16 + (l >> 2);
    const int kb = kt * 64 + s * 16 + 2 * t;
    const float* w0 = W + (size_t)kb * Nin + c0;
    uint4 u;
    u.x = f2h2(w0[0], w0[Nin]);
    u.y = f2h2(w0[(size_t)8 * Nin], w0[(size_t)9 * Nin]);
    u.z = f2h2(w0[8], w0[Nin + 8]);
    u.w = f2h2(w0[(size_t)8 * Nin + 8], w0[(size_t)9 * Nin + 8]);
    out[idx] = u;
  }
}

// pack roped K and V into flash fragment blobs, once per (kvh, kv-tile)
__global__ __launch_bounds__(256) void pack_kv(const float* __restrict__ qkv) {
  const int t = blockIdx.x;    // kv tile 0..63
  const int kvh = blockIdx.y;  // 0..3
  const int tid = threadIdx.x;
  const float* Kp = qkv + DM + kvh * HD;
  const float* Vp = qkv + DM + NKV * HD + kvh * HD;
  uint2* ko = g_kf + ((size_t)kvh * 64 + t) * 2048;
  uint2* vo = g_vf + ((size_t)kvh * 64 + t) * 2048;
#pragma unroll
  for (int e = tid; e < 2048; e += 256) {
    const int l = e & 31, g = l >> 2, tt = l & 3;
    {
      const int nt = (e >> 5) & 7, ks = e >> 8;
      const float* kr = Kp + (size_t)(t * 64 + 8 * nt + g) * QKVW + 16 * ks + 2 * tt;
      uint2 u;
      u.x = f2h2(kr[0], kr[1]);
      u.y = f2h2(kr[8], kr[9]);
      ko[e] = u;
    }
    {
      const int nt = (e >> 5) & 15, ks = e >> 9;
      const int d = nt * 8 + g;
      const float* vr = Vp + (size_t)(t * 64 + ks * 16 + 2 * tt) * QKVW + d;
      uint2 u;
      u.x = f2h2(vr[0], vr[QKVW]);
      u.y = f2h2(vr[(size_t)8 * QKVW], vr[(size_t)9 * QKVW]);
      vo[e] = u;
    }
  }
}

// ---------------- packed fp16 GEMM: A via smem cp.async, B via direct LDG ---
// 128x128 tile, BK=64, 256 threads. Stage = A only (16KB) x2 = 32KB smem.
// B fragments LDG.128'd straight from the packed blob (L2-resident),
// software-prefetched one s-step ahead.
#define GEMM_SMEM (2 * 16384)
__global__ __launch_bounds__(256, 2) void gemm_f16(
    const uint4* __restrict__ Ap, const uint4* __restrict__ Bp,
    float* __restrict__ C, int N, int K) {
  extern __shared__ uint32_t sm[];
  const int tid = threadIdx.x;
  const int l = tid & 31;
  const int w = tid >> 5;
  const int warp_m = w >> 2;
  const int warp_n = w & 3;
  const int T = K >> 6;

  const uint4* Ag = Ap + (size_t)blockIdx.y * T * 1024;
  // lane-resolved B pointer: Bw[kt*1024 + s*256 + {0,32}]
  const uint4* Bw = Bp + (size_t)blockIdx.x * T * 1024 + (warp_n * 2) * 32 + l;
  const uint32_t smu = smem_u32(sm);

  float acc[4][4][4];
#pragma unroll
  for (int mt = 0; mt < 4; mt++)
#pragma unroll
    for (int nt = 0; nt < 4; nt++)
#pragma unroll
      for (int c = 0; c < 4; c++) acc[mt][nt][c] = 0.0f;

#define CPT(t)                                                                 \
  do {                                                                         \
    const uint32_t ba = smu + ((t) & 1) * 16384;                               \
    const uint4* ga = Ag + (size_t)(t) * 1024;                                 \
    _Pragma("unroll") for (int j = 0; j < 4; j++)                              \
        cp16(ba + (tid + 256 * j) * 16, ga + tid + 256 * j);                   \
    asm volatile("cp.async.commit_group;");                                    \
  } while (0)

  CPT(0);

  // prefetch B for (t=0, s=0)
  uint4 b01 = Bw[0];
  uint4 b23 = Bw[32];

  const int last_idx = (T - 1) * 1024 + 3 * 256;

  for (int t = 0; t < T; t++) {
    asm volatile("cp.async.wait_group 0;");
    __syncthreads();            // A stage t ready; all warps done with t-1
    if (t + 1 < T) CPT(t + 1);  // overlaps compute(t)

    const uint4* smA = (const uint4*)(sm + (t & 1) * 4096);
#pragma unroll
    for (int s = 0; s < 4; s++) {
      uint4 af[4];
#pragma unroll
      for (int mt = 0; mt < 4; mt++)
        af[mt] = smA[(s * 8 + warp_m * 4 + mt) * 32 + l];
      // prefetch next s-step's B (clamped at the very end)
      int nidx = t * 1024 + s * 256 + 256;     // (t, s+1) / rolls into (t+1, 0)
      if (nidx > last_idx) nidx = 0;
      uint4 nb01 = Bw[nidx];
      uint4 nb23 = Bw[nidx + 32];

      const uint32_t bfr[4][2] = {
          {b01.x, b01.y}, {b01.z, b01.w}, {b23.x, b23.y}, {b23.z, b23.w}};
#pragma unroll
      for (int mt = 0; mt < 4; mt++) {
        const uint32_t a[4] = {af[mt].x, af[mt].y, af[mt].z, af[mt].w};
#pragma unroll
        for (int nt = 0; nt < 4; nt++) mma_f16(acc[mt][nt], a, bfr[nt]);
      }
      b01 = nb01;
      b23 = nb23;
    }
  }

  const int bm = blockIdx.y * 128;
  const int bn = blockIdx.x * 128;
#pragma unroll
  for (int mt = 0; mt < 4; mt++) {
    const int row = bm + warp_m * 64 + mt * 16 + (l >> 2);
#pragma unroll
    for (int nt = 0; nt < 4; nt++) {
      const int col = bn + warp_n * 32 + nt * 8 + 2 * (l & 3);
      float2 lo = {acc[mt][nt][0], acc[mt][nt][1]};
      float2 hi = {acc[mt][nt][2], acc[mt][nt][3]};
      *(float2*)(C + (size_t)row * N + col) = lo;
      *(float2*)(C + (size_t)(row + 8) * N + col) = hi;
    }
  }
}

// ---------------- RoPE: table + apply ----------------------------------------
__global__ __launch_bounds__(256) void rope_table_kernel() {
  const int idx = blockIdx.x * 256 + threadIdx.x;
  const int s = idx >> 6, d = idx & 63;
  float inv = powf(10000.0f, -((float)(2 * d) / 128.0f));
  float sn, cs;
  sincosf((float)s * inv, &sn, &cs);
  g_rope[idx] = make_float2(cs, sn);
}

__global__ __launch_bounds__(256) void rope_apply_kernel(float* __restrict__ qkv) {
  const int tid = threadIdx.x;
  const int d = tid & 63, si = tid >> 6;
  const int s = blockIdx.x * 4 + si;
  const int hh = blockIdx.y;
  float* ptr = qkv + (size_t)s * QKVW +
               (hh < NH ? hh * HD : DM + (hh - NH) * HD);
  const float2 cs = g_rope[s * 64 + d];
  const float x0 = ptr[d];
  const float x1 = ptr[d + 64];
  ptr[d] = x0 * cs.x - x1 * cs.y;
  ptr[d + 64] = x1 * cs.x + x0 * cs.y;
}

// ---------------- Flash attention, fp16 m16n8k16, cp.async KV pipeline ------
#define BQ 128
#define BKV 64
#define F_SMEM_BYTES (32768 + 2 * 32768)

__global__ __launch_bounds__(256) void flash_f16_kernel(
    const float* __restrict__ QKV, uint4* __restrict__ Pout) {
  extern __shared__ uint32_t fsm[];
  uint4* Qf = (uint4*)fsm;                 // 8192 words

  const int h = blockIdx.y;
  const int qb = gridDim.x - 1 - blockIdx.x;  // long blocks first
  const int q0 = qb * BQ;
  const int kvh = h >> 2;
  const int tid = threadIdx.x;
  const int l = tid & 31;
  const int w = tid >> 5;
  const int g = l >> 2;
  const int tt = l & 3;

  const float* Qp = QKV + h * HD;
  const float scale = 0.08838834764831845f;
  const uint32_t smu = smem_u32(fsm);
  const uint4* kvbase_k = (const uint4*)(g_kf + (size_t)kvh * 64 * 2048);
  const uint4* kvbase_v = (const uint4*)(g_vf + (size_t)kvh * 64 * 2048);

#define CPKV(t)                                                                \
  do {                                                                         \
    const uint32_t ba = smu + 32768 + ((t) & 1) * 32768;                       \
    const uint4* kg = kvbase_k + (size_t)(t) * 1024;                           \
    const uint4* vg = kvbase_v + (size_t)(t) * 1024;                           \
    _Pragma("unroll") for (int j = 0; j < 4; j++) {                            \
      cp16(ba + (tid + 256 * j) * 16, kg + tid + 256 * j);                     \
      cp16(ba + 16384 + (tid + 256 * j) * 16, vg + tid + 256 * j);             \
    }                                                                          \
    asm volatile("cp.async.commit_group;");                                    \
  } while (0)

  CPKV(0);

#pragma unroll
  for (int i = 0; i < 8; i++) {
    const float* r0 = Qp + (size_t)(q0 + 16 * w + g) * QKVW + 16 * i + 2 * tt;
    const float* r1 = r0 + (size_t)8 * QKVW;
    float2 x0 = *(const float2*)r0;
    float2 x1 = *(const float2*)(r0 + 8);
    float2 y0 = *(const float2*)r1;
    float2 y1 = *(const float2*)(r1 + 8);
    uint4 u;
    u.x = f2h2(x0.x * scale, x0.y * scale);
    u.y = f2h2(y0.x * scale, y0.y * scale);
    u.z = f2h2(x1.x * scale, x1.y * scale);
    u.w = f2h2(y1.x * scale, y1.y * scale);
    Qf[tid + 256 * i] = u;
  }

  float m_i0 = -3.0e38f, m_i1 = -3.0e38f;
  float l_i0 = 0.0f, l_i1 = 0.0f;
  float O[16][4];
#pragma unroll
  for (int nt = 0; nt < 16; nt++)
#pragma unroll
    for (int c = 0; c < 4; c++) O[nt][c] = 0.0f;

  const int ntiles = (q0 + BQ) / BKV;

  for (int t = 0; t < ntiles; t++) {
    asm volatile("cp.async.wait_group 0;");
    __syncthreads();
    if (t + 1 < ntiles) CPKV(t + 1);

    const uint2* Kf = (const uint2*)(fsm + 8192 + (t & 1) * 8192);
    const uint2* Vf = (const uint2*)(fsm + 8192 + (t & 1) * 8192 + 4096);

    const bool active = (t * BKV <= q0 + 16 * w + 15);
    if (active) {
      float S[8][4];
#pragma unroll
      for (int nt = 0; nt < 8; nt++)
#pragma unroll
        for (int c = 0; c < 4; c++) S[nt][c] = 0.0f;
#pragma unroll
      for (int ks = 0; ks < 8; ks++) {
        uint4 af = Qf[(ks * 8 + w) * 32 + l];
        const uint32_t a[4] = {af.x, af.y, af.z, af.w};
#pragma unroll
        for (int nt = 0; nt < 8; nt++) {
          uint2 bf = Kf[(ks * 8 + nt) * 32 + l];
          const uint32_t b[2] = {bf.x, bf.y};
          mma_f16(S[nt], a, b);
        }
      }

      const int rowg0 = q0 + 16 * w + g;
      const int rowg1 = rowg0 + 8;
      if (t * BKV + BKV - 1 > q0 + 16 * w) {
#pragma unroll
        for (int nt = 0; nt < 8; nt++) {
          const int c0 = t * BKV + nt * 8 + 2 * tt;
          if (c0 > rowg0) S[nt][0] = -3.0e38f;
          if (c0 + 1 > rowg0) S[nt][1] = -3.0e38f;
          if (c0 > rowg1) S[nt][2] = -3.0e38f;
          if (c0 + 1 > rowg1) S[nt][3] = -3.0e38f;
        }
      }

      float mx0 = -3.0e38f, mx1 = -3.0e38f;
#pragma unroll
      for (int nt = 0; nt < 8; nt++) {
        mx0 = fmaxf(mx0, fmaxf(S[nt][0], S[nt][1]));
        mx1 = fmaxf(mx1, fmaxf(S[nt][2], S[nt][3]));
      }
      mx0 = fmaxf(mx0, __shfl_xor_sync(0xffffffffu, mx0, 1));
      mx0 = fmaxf(mx0, __shfl_xor_sync(0xffffffffu, mx0, 2));
      mx1 = fmaxf(mx1, __shfl_xor_sync(0xffffffffu, mx1, 1));
      mx1 = fmaxf(mx1, __shfl_xor_sync(0xffffffffu, mx1, 2));
      const float mn0 = fmaxf(m_i0, mx0);
      const float mn1 = fmaxf(m_i1, mx1);

      float rs0 = 0.0f, rs1 = 0.0f;
#pragma unroll
      for (int nt = 0; nt < 8; nt++) {
        S[nt][0] = __expf(S[nt][0] - mn0);
        S[nt][1] = __expf(S[nt][1] - mn0);
        S[nt][2] = __expf(S[nt][2] - mn1);
        S[nt][3] = __expf(S[nt][3] - mn1);
        rs0 += S[nt][0] + S[nt][1];
        rs1 += S[nt][2] + S[nt][3];
      }
      rs0 += __shfl_xor_sync(0xffffffffu, rs0, 1);
      rs0 += __shfl_xor_sync(0xffffffffu, rs0, 2);
      rs1 += __shfl_xor_sync(0xffffffffu, rs1, 1);
      rs1 += __shfl_xor_sync(0xffffffffu, rs1, 2);
      const float alpha0 = __expf(m_i0 - mn0);
      const float alpha1 = __expf(m_i1 - mn1);
      l_i0 = l_i0 * alpha0 + rs0;
      l_i1 = l_i1 * alpha1 + rs1;
      m_i0 = mn0;
      m_i1 = mn1;
#pragma unroll
      for (int nt = 0; nt < 16; nt++) {
        O[nt][0] *= alpha0;
        O[nt][1] *= alpha0;
        O[nt][2] *= alpha1;
        O[nt][3] *= alpha1;
      }

#pragma unroll
      for (int ks = 0; ks < 4; ks++) {
        const uint32_t a[4] = {f2h2(S[2 * ks][0], S[2 * ks][1]),
                               f2h2(S[2 * ks][2], S[2 * ks][3]),
                               f2h2(S[2 * ks + 1][0], S[2 * ks + 1][1]),
                               f2h2(S[2 * ks + 1][2], S[2 * ks + 1][3])};
#pragma unroll
        for (int nt = 0; nt < 16; nt++) {
          uint2 bf = Vf[(ks * 16 + nt) * 32 + l];
          const uint32_t b[2] = {bf.x, bf.y};
          mma_f16(O[nt], a, b);
        }
      }
    }
    __syncthreads();
  }

  const float inv0 = 1.0f / l_i0;
  const float inv1 = 1.0f / l_i1;
  uint4* outp = Pout + (size_t)qb * 32 * 1024;
#pragma unroll
  for (int p = 0; p < 8; p++) {
    const int nt = 2 * p;
    const int kt = 2 * h + (nt >> 3);
    const int s = (nt & 7) >> 1;
    uint4 u;
    u.x = f2h2(O[nt][0] * inv0, O[nt][1] * inv0);
    u.y = f2h2(O[nt][2] * inv1, O[nt][3] * inv1);
    u.z = f2h2(O[nt + 1][0] * inv0, O[nt + 1][1] * inv0);
    u.w = f2h2(O[nt + 1][2] * inv1, O[nt + 1][3] * inv1);
    outp[(size_t)kt * 1024 + s * 256 + w * 32 + l] = u;
  }
}

// ---------------- launch ----------------------------------------------------
extern "C" void kernel_launch(void* const* d_in, const int* in_sizes, int n_in,
                              void* d_out, int out_size) {
  const float* x = (const float*)d_in[0];
  const float* wq = (const float*)d_in[1];
  const float* wk = (const float*)d_in[2];
  const float* wv = (const float*)d_in[3];
  const float* wo = (const float*)d_in[4];
  float* out = (float*)d_out;

  float* qkv_p;
  uint4 *pa, *pattn, *pbqkv, *pbwo;
  cudaGetSymbolAddress((void**)&qkv_p, g_qkv);
  cudaGetSymbolAddress((void**)&pa, g_pa);
  cudaGetSymbolAddress((void**)&pattn, g_pattn);
  cudaGetSymbolAddress((void**)&pbqkv, g_pbqkv);
  cudaGetSymbolAddress((void**)&pbwo, g_pbwo);

  cudaFuncSetAttribute(gemm_f16, cudaFuncAttributeMaxDynamicSharedMemorySize,
                       GEMM_SMEM);
  cudaFuncSetAttribute(flash_f16_kernel,
                       cudaFuncAttributeMaxDynamicSharedMemorySize,
                       F_SMEM_BYTES);

  // packs
  pack_a_f16<<<dim3(DM / 64, S_LEN / 128), 256>>>(x, pa, DM);
  pack_b_f16<<<dim3(DM / 64, 16), 256>>>(wq, pbqkv, DM, 0);
  pack_b_f16<<<dim3(DM / 64, 4), 256>>>(wk, pbqkv, NKV * HD, 16);
  pack_b_f16<<<dim3(DM / 64, 4), 256>>>(wv, pbqkv, NKV * HD, 20);
  pack_b_f16<<<dim3(DM / 64, 16), 256>>>(wo, pbwo, DM, 0);

  // fused QKV projection: [4096,2048] x [2048,3072]
  gemm_f16<<<dim3(QKVW / 128, S_LEN / 128), 256, GEMM_SMEM>>>(pa, pbqkv, qkv_p,
                                                              QKVW, DM);

  // RoPE table + apply
  rope_table_kernel<<<(S_LEN * 64) / 256, 256>>>();
  rope_apply_kernel<<<dim3(S_LEN / 4, NH + NKV), 256>>>(qkv_p);

  // pack roped K/V into fp16 fragment blobs (once)
  pack_kv<<<dim3(S_LEN / BKV, NKV), 256>>>(qkv_p);

  // causal flash attention (fp16 mma, cp.async KV pipeline, packed-out)
  flash_f16_kernel<<<dim3(S_LEN / BQ, NH), 256, F_SMEM_BYTES>>>(qkv_p, pattn);

  // output projection (reads flash's packed output directly)
  gemm_f16<<<dim3(DM / 128, S_LEN / 128), 256, GEMM_SMEM>>>(pattn, pbwo, out,
                                                            DM, DM);
}